// round 16
// baseline (speedup 1.0000x reference)
#include <cuda_runtime.h>
#include <cuda_bf16.h>
#include <cuda_fp16.h>
#include <stdint.h>

#define NB 8
#define NT 2048
#define NF 256
#define TOK (NB * NT)

// ------------------------------- device globals ---------------------------
__device__ __align__(128) __nv_bfloat16 g_fhi[TOK * NF], g_flo[TOK * NF];
__device__ __align__(128) __half g_fT16[(size_t)NB * NF * NT];
__device__ __align__(128) __nv_bfloat16 g_Ghi[TOK * NF], g_Glo[TOK * NF];
__device__ __align__(128) __nv_bfloat16 g_Mhi[NF * NF], g_Mlo[NF * NF];
__device__ __align__(128) __half g_p16[(size_t)NB * NT * NT];
__device__ __align__(128) float g_mpart[8 * TOK];
__device__ __align__(128) float g_lpart[8 * TOK];
__device__ __align__(128) float g_scale[8 * TOK];
__device__ __align__(128) float g_l[TOK];
__device__ __align__(128) float g_beta[TOK];
__device__ __align__(128) float g_u[NF];
__device__ float g_fsump[NB * 64 * NF];
__device__ float g_v[NB * NF];
__device__ float g_cc[NB];

// ------------------------------ helpers -----------------------------------
__device__ __forceinline__ uint32_t smem_u32(const void* p) {
    uint32_t a;
    asm("{ .reg .u64 t; cvta.to.shared.u64 t, %1; cvt.u32.u64 %0, t; }" : "=r"(a) : "l"(p));
    return a;
}
__device__ __forceinline__ uint32_t pack2(__nv_bfloat16 a, __nv_bfloat16 b) {
    __nv_bfloat162 t = __halves2bfloat162(a, b);
    return *reinterpret_cast<uint32_t*>(&t);
}
__device__ __forceinline__ uint32_t pack2h(__half a, __half b) {
    __half2 t = __halves2half2(a, b);
    return *reinterpret_cast<uint32_t*>(&t);
}
__device__ __forceinline__ float fast_exp(float x) {
    float t = x * 1.4426950408889634f;
    t = fmaxf(t, -125.0f);
    float r = t + 12582912.0f;
    int ei = __float_as_int(r) - 0x4B400000;
    float f = t - (r - 12582912.0f);
    float p = 1.5403530e-4f;
    p = fmaf(p, f, 1.3333558e-3f);
    p = fmaf(p, f, 9.6181291e-3f);
    p = fmaf(p, f, 5.5504109e-2f);
    p = fmaf(p, f, 2.4022651e-1f);
    p = fmaf(p, f, 6.9314718e-1f);
    p = fmaf(p, f, 1.0f);
    return p * __int_as_float((ei + 127) << 23);
}
__device__ __forceinline__ void cpa16(uint32_t d, const void* s) {
    asm volatile("cp.async.cg.shared.global [%0], [%1], 16;" :: "r"(d), "l"(s));
}
__device__ __forceinline__ void ldsm4(uint32_t a, uint32_t& r0, uint32_t& r1, uint32_t& r2, uint32_t& r3) {
    asm volatile("ldmatrix.sync.aligned.m8n8.x4.shared.b16 {%0,%1,%2,%3}, [%4];"
                 : "=r"(r0), "=r"(r1), "=r"(r2), "=r"(r3) : "r"(a));
}
__device__ __forceinline__ void mma_bf(float* c, const uint32_t* a, uint32_t b0, uint32_t b1) {
    asm volatile("mma.sync.aligned.m16n8k16.row.col.f32.bf16.bf16.f32 "
                 "{%0,%1,%2,%3},{%4,%5,%6,%7},{%8,%9},{%0,%1,%2,%3};"
                 : "+f"(c[0]), "+f"(c[1]), "+f"(c[2]), "+f"(c[3])
                 : "r"(a[0]), "r"(a[1]), "r"(a[2]), "r"(a[3]), "r"(b0), "r"(b1));
}
__device__ __forceinline__ void mma_hf(float* c, const uint32_t* a, uint32_t b0, uint32_t b1) {
    asm volatile("mma.sync.aligned.m16n8k16.row.col.f32.f16.f16.f32 "
                 "{%0,%1,%2,%3},{%4,%5,%6,%7},{%8,%9},{%0,%1,%2,%3};"
                 : "+f"(c[0]), "+f"(c[1]), "+f"(c[2]), "+f"(c[3])
                 : "r"(a[0]), "r"(a[1]), "r"(a[2]), "r"(a[3]), "r"(b0), "r"(b1));
}

template <int ROWS>
__device__ __forceinline__ void load_slice(uint32_t dst, const __nv_bfloat16* __restrict__ src, int ld) {
#pragma unroll
    for (int it = 0; it < ROWS * 8 / 256; it++) {
        int idx = it * 256 + threadIdx.x;
        int r = idx >> 3, c = idx & 7;
        uint32_t d = dst + ((r >> 3) << 10) + ((r & 7) << 7) + ((uint32_t)(c ^ (r & 7)) << 4);
        cpa16(d, src + (size_t)r * ld + c * 8);
    }
}
__device__ __forceinline__ uint32_t frag_addr(uint32_t base, int r, int c) {
    return base + ((r >> 3) << 10) + ((r & 7) << 7) + ((uint32_t)(c ^ (r & 7)) << 4);
}

// ---------------------------------------------------------------------------
// Split-bf16 GEMM (MODE 0/1): D[128,256], 256 thr, 8 warps (2M x 4N), warp 64x64.
// MODE 0: G = feat @ M~^T, K=256 -> G hi/lo
// MODE 1: G1 = G @ feat^T + beta, K=256 -> P_local fp16 + m,l partials
// ---------------------------------------------------------------------------
template <int MODE>
__global__ void __launch_bounds__(256, 1) gemm_kernel(float* __restrict__ out) {
    extern __shared__ char smem[];
    uint32_t sb = smem_u32(smem);
    const int tid = threadIdx.x, wid = tid >> 5, lane = tid & 31;
    constexpr int NS = 4;
    constexpr uint32_t STAGE = 98304u;

    const __nv_bfloat16 *Ahi, *Alo, *Bhi, *Blo;
    int m0, n0 = 0, b = 0;
    if (MODE == 0) {
        m0 = blockIdx.x * 128;
        Ahi = g_fhi + (size_t)m0 * NF; Alo = g_flo + (size_t)m0 * NF;
        Bhi = g_Mhi; Blo = g_Mlo;
    } else {
        n0 = blockIdx.x * 256; m0 = blockIdx.y * 128; b = blockIdx.z;
        Ahi = g_Ghi + (size_t)(b * NT + m0) * NF; Alo = g_Glo + (size_t)(b * NT + m0) * NF;
        Bhi = g_fhi + (size_t)(b * NT + n0) * NF; Blo = g_flo + (size_t)(b * NT + n0) * NF;
    }

    const int wm = (wid & 1) << 6;
    const int wn = (wid >> 1) << 6;
    const int g = lane >> 2, q = lane & 3;

    float acc[4][8][4];
#pragma unroll
    for (int i = 0; i < 4; i++)
#pragma unroll
        for (int j = 0; j < 8; j++)
#pragma unroll
            for (int u = 0; u < 4; u++) acc[i][j][u] = 0.f;

    auto load_stage = [&](int s) {
        uint32_t base = sb + (uint32_t)(s & 1) * STAGE;
        load_slice<128>(base,          Ahi + s * 64, NF);
        load_slice<128>(base + 16384,  Alo + s * 64, NF);
        load_slice<256>(base + 32768,  Bhi + s * 64, NF);
        load_slice<256>(base + 65536,  Blo + s * 64, NF);
        asm volatile("cp.async.commit_group;");
    };

    load_stage(0);

#pragma unroll 1
    for (int s = 0; s < NS; s++) {
        if (s + 1 < NS) {
            load_stage(s + 1);
            asm volatile("cp.async.wait_group 1;");
        } else {
            asm volatile("cp.async.wait_group 0;");
        }
        __syncthreads();

        uint32_t base = sb + (uint32_t)(s & 1) * STAGE;
        const int ar = wm + (lane & 15), br = wn + (lane & 15), ch = lane >> 4;
#pragma unroll
        for (int k = 0; k < 4; k++) {
            const int c = 2 * k + ch;
            uint32_t ah[4][4], bh[4][4], tt[4][4];
#pragma unroll
            for (int mt = 0; mt < 4; mt++)
                ldsm4(frag_addr(base, ar + 16 * mt, c), ah[mt][0], ah[mt][1], ah[mt][2], ah[mt][3]);
#pragma unroll
            for (int nt = 0; nt < 4; nt++)
                ldsm4(frag_addr(base + 32768u, br + 16 * nt, c), bh[nt][0], bh[nt][1], bh[nt][2], bh[nt][3]);
            // pass hh
#pragma unroll
            for (int nt = 0; nt < 4; nt++)
#pragma unroll
                for (int mt = 0; mt < 4; mt++) {
                    mma_bf(acc[mt][2 * nt],     ah[mt], bh[nt][0], bh[nt][2]);
                    mma_bf(acc[mt][2 * nt + 1], ah[mt], bh[nt][1], bh[nt][3]);
                }
            // pass hl: B-lo, reuse ah
#pragma unroll
            for (int nt = 0; nt < 4; nt++)
                ldsm4(frag_addr(base + 65536u, br + 16 * nt, c), tt[nt][0], tt[nt][1], tt[nt][2], tt[nt][3]);
#pragma unroll
            for (int nt = 0; nt < 4; nt++)
#pragma unroll
                for (int mt = 0; mt < 4; mt++) {
                    mma_bf(acc[mt][2 * nt],     ah[mt], tt[nt][0], tt[nt][2]);
                    mma_bf(acc[mt][2 * nt + 1], ah[mt], tt[nt][1], tt[nt][3]);
                }
            // pass lh: A-lo, reuse bh
#pragma unroll
            for (int mt = 0; mt < 4; mt++)
                ldsm4(frag_addr(base + 16384u, ar + 16 * mt, c), tt[mt][0], tt[mt][1], tt[mt][2], tt[mt][3]);
#pragma unroll
            for (int nt = 0; nt < 4; nt++)
#pragma unroll
                for (int mt = 0; mt < 4; mt++) {
                    mma_bf(acc[mt][2 * nt],     tt[mt], bh[nt][0], bh[nt][2]);
                    mma_bf(acc[mt][2 * nt + 1], tt[mt], bh[nt][1], bh[nt][3]);
                }
        }
        __syncthreads();
    }

    // ------------------------------ epilogues ------------------------------
    if (MODE == 0) {
#pragma unroll
        for (int mt = 0; mt < 4; mt++) {
            int ra = m0 + wm + 16 * mt + g, rb = ra + 8;
#pragma unroll
            for (int nt = 0; nt < 8; nt++) {
                int col = wn + nt * 8 + 2 * q;
                float v0 = acc[mt][nt][0], v1 = acc[mt][nt][1];
                float v2 = acc[mt][nt][2], v3 = acc[mt][nt][3];
                __nv_bfloat16 h0 = __float2bfloat16(v0), h1 = __float2bfloat16(v1);
                __nv_bfloat16 h2 = __float2bfloat16(v2), h3 = __float2bfloat16(v3);
                *reinterpret_cast<uint32_t*>(&g_Ghi[(size_t)ra * NF + col]) = pack2(h0, h1);
                *reinterpret_cast<uint32_t*>(&g_Ghi[(size_t)rb * NF + col]) = pack2(h2, h3);
                *reinterpret_cast<uint32_t*>(&g_Glo[(size_t)ra * NF + col]) =
                    pack2(__float2bfloat16(v0 - __bfloat162float(h0)), __float2bfloat16(v1 - __bfloat162float(h1)));
                *reinterpret_cast<uint32_t*>(&g_Glo[(size_t)rb * NF + col]) =
                    pack2(__float2bfloat16(v2 - __bfloat162float(h2)), __float2bfloat16(v3 - __bfloat162float(h3)));
            }
        }
    } else {
        float* ls  = reinterpret_cast<float*>(smem);
        float* ls2 = reinterpret_cast<float*>(smem) + 512;
        float2 be[8];
#pragma unroll
        for (int nt = 0; nt < 8; nt++)
            be[nt] = *reinterpret_cast<const float2*>(&g_beta[b * NT + n0 + wn + nt * 8 + 2 * q]);
#pragma unroll
        for (int mt = 0; mt < 4; mt++) {
            float ma = -1e30f, mb = -1e30f;
#pragma unroll
            for (int nt = 0; nt < 8; nt++) {
                acc[mt][nt][0] += be[nt].x; acc[mt][nt][1] += be[nt].y;
                acc[mt][nt][2] += be[nt].x; acc[mt][nt][3] += be[nt].y;
                ma = fmaxf(ma, fmaxf(acc[mt][nt][0], acc[mt][nt][1]));
                mb = fmaxf(mb, fmaxf(acc[mt][nt][2], acc[mt][nt][3]));
            }
#pragma unroll
            for (int off = 1; off <= 2; off <<= 1) {
                ma = fmaxf(ma, __shfl_xor_sync(0xffffffffu, ma, off));
                mb = fmaxf(mb, __shfl_xor_sync(0xffffffffu, mb, off));
            }
            if (q == 0) {
                int lr = wm + 16 * mt + g;
                ls[(size_t)lr * 4 + (wid >> 1)] = ma;
                ls[(size_t)(lr + 8) * 4 + (wid >> 1)] = mb;
            }
        }
        __syncthreads();
#pragma unroll
        for (int mt = 0; mt < 4; mt++) {
            int lra = wm + 16 * mt + g, lrb = lra + 8;
            float mla = fmaxf(fmaxf(ls[lra * 4], ls[lra * 4 + 1]),
                              fmaxf(ls[lra * 4 + 2], ls[lra * 4 + 3]));
            float mlb = fmaxf(fmaxf(ls[lrb * 4], ls[lrb * 4 + 1]),
                              fmaxf(ls[lrb * 4 + 2], ls[lrb * 4 + 3]));
            int ra = m0 + lra, rb = m0 + lrb;
            float sa = 0.f, sbn = 0.f;
#pragma unroll
            for (int nt = 0; nt < 8; nt++) {
                int col = n0 + wn + nt * 8 + 2 * q;
                float p0 = fast_exp(acc[mt][nt][0] - mla);
                float p1 = fast_exp(acc[mt][nt][1] - mla);
                float p2 = fast_exp(acc[mt][nt][2] - mlb);
                float p3 = fast_exp(acc[mt][nt][3] - mlb);
                sa += p0 + p1; sbn += p2 + p3;
                *reinterpret_cast<uint32_t*>(&g_p16[((size_t)b * NT + ra) * NT + col]) =
                    pack2h(__float2half(p0), __float2half(p1));
                *reinterpret_cast<uint32_t*>(&g_p16[((size_t)b * NT + rb) * NT + col]) =
                    pack2h(__float2half(p2), __float2half(p3));
            }
#pragma unroll
            for (int off = 1; off <= 2; off <<= 1) {
                sa += __shfl_xor_sync(0xffffffffu, sa, off);
                sbn += __shfl_xor_sync(0xffffffffu, sbn, off);
            }
            if (q == 0) {
                ls2[(size_t)lra * 4 + (wid >> 1)] = sa;
                ls2[(size_t)lrb * 4 + (wid >> 1)] = sbn;
            }
        }
        __syncthreads();
        if (tid < 128) {
            float m = fmaxf(fmaxf(ls[tid * 4], ls[tid * 4 + 1]),
                            fmaxf(ls[tid * 4 + 2], ls[tid * 4 + 3]));
            float l = ls2[tid * 4] + ls2[tid * 4 + 1] + ls2[tid * 4 + 2] + ls2[tid * 4 + 3];
            g_mpart[(size_t)blockIdx.x * TOK + b * NT + m0 + tid] = m;
            g_lpart[(size_t)blockIdx.x * TOK + b * NT + m0 + tid] = l;
        }
    }
}

// ---------------------------------------------------------------------------
// G2: out = (P_local * scale) @ featT / l. CTA 128x128, 256 thr,
// warp grid 2M x 4N (warp tile 64x32), 2 CTAs/SM, grid (16,2,8) = one wave.
// ---------------------------------------------------------------------------
__global__ void __launch_bounds__(256, 2) gemm2_kernel(float* __restrict__ out) {
    extern __shared__ char smem[];
    uint32_t sb = smem_u32(smem);
    const int tid = threadIdx.x, wid = tid >> 5, lane = tid & 31;
    constexpr int NS = 32;
    constexpr uint32_t STAGE = 32768u;

    const int m0 = blockIdx.x * 128, n0 = blockIdx.y * 128, b = blockIdx.z;
    const __nv_bfloat16* A = reinterpret_cast<const __nv_bfloat16*>(g_p16 + ((size_t)b * NT + m0) * NT);
    const __nv_bfloat16* B = reinterpret_cast<const __nv_bfloat16*>(g_fT16 + ((size_t)b * NF + n0) * NT);

    const int wm = (wid & 1) << 6;
    const int wn = (wid >> 1) << 5;
    const int g = lane >> 2, q = lane & 3;

    float acc[4][4][4];
#pragma unroll
    for (int i = 0; i < 4; i++)
#pragma unroll
        for (int j = 0; j < 4; j++)
#pragma unroll
            for (int u = 0; u < 4; u++) acc[i][j][u] = 0.f;

    auto load_stage = [&](int s) {
        uint32_t base = sb + (uint32_t)(s & 1) * STAGE;
        load_slice<128>(base,          A + s * 64, NT);
        load_slice<128>(base + 16384,  B + s * 64, NT);
        asm volatile("cp.async.commit_group;");
    };

    load_stage(0);

    __half2 sca2[4], scb2[4];

#pragma unroll 1
    for (int s = 0; s < NS; s++) {
        if ((s & 3) == 0) {
            int tile = s >> 2;
#pragma unroll
            for (int mt = 0; mt < 4; mt++) {
                int ra = m0 + wm + 16 * mt + g;
                sca2[mt] = __float2half2_rn(g_scale[(size_t)tile * TOK + b * NT + ra]);
                scb2[mt] = __float2half2_rn(g_scale[(size_t)tile * TOK + b * NT + ra + 8]);
            }
        }
        if (s + 1 < NS) {
            load_stage(s + 1);
            asm volatile("cp.async.wait_group 1;");
        } else {
            asm volatile("cp.async.wait_group 0;");
        }
        __syncthreads();

        uint32_t base = sb + (uint32_t)(s & 1) * STAGE;
        const int ar = wm + (lane & 15), br = wn + (lane & 15), ch = lane >> 4;
#pragma unroll
        for (int k = 0; k < 4; k++) {
            const int c = 2 * k + ch;
            uint32_t a4[4][4], b4[2][4];
#pragma unroll
            for (int mt = 0; mt < 4; mt++) {
                ldsm4(frag_addr(base, ar + 16 * mt, c), a4[mt][0], a4[mt][1], a4[mt][2], a4[mt][3]);
                __half2* ap = reinterpret_cast<__half2*>(a4[mt]);
                ap[0] = __hmul2(ap[0], sca2[mt]);
                ap[2] = __hmul2(ap[2], sca2[mt]);
                ap[1] = __hmul2(ap[1], scb2[mt]);
                ap[3] = __hmul2(ap[3], scb2[mt]);
            }
#pragma unroll
            for (int j = 0; j < 2; j++)
                ldsm4(frag_addr(base + 16384u, br + 16 * j, c), b4[j][0], b4[j][1], b4[j][2], b4[j][3]);
#pragma unroll
            for (int j = 0; j < 2; j++)
#pragma unroll
                for (int mt = 0; mt < 4; mt++) {
                    mma_hf(acc[mt][2 * j],     a4[mt], b4[j][0], b4[j][2]);
                    mma_hf(acc[mt][2 * j + 1], a4[mt], b4[j][1], b4[j][3]);
                }
        }
        __syncthreads();
    }

#pragma unroll
    for (int mt = 0; mt < 4; mt++) {
        int ra = m0 + wm + 16 * mt + g, rb = ra + 8;
        float ia = 1.0f / g_l[b * NT + ra];
        float ib = 1.0f / g_l[b * NT + rb];
#pragma unroll
        for (int nt = 0; nt < 4; nt++) {
            int col = n0 + wn + nt * 8 + 2 * q;
            float2 wa, wb;
            wa.x = acc[mt][nt][0] * ia; wa.y = acc[mt][nt][1] * ia;
            wb.x = acc[mt][nt][2] * ib; wb.y = acc[mt][nt][3] * ib;
            *reinterpret_cast<float2*>(&out[((size_t)b * NT + ra) * NF + col]) = wa;
            *reinterpret_cast<float2*>(&out[((size_t)b * NT + rb) * NF + col]) = wb;
        }
    }
}

// ---------------------- lsum: exact row max/sum + scales --------------------
__global__ void lsum_kernel() {
    int row = blockIdx.x * 256 + threadIdx.x;
    float mi[8], m = -1e30f;
#pragma unroll
    for (int i = 0; i < 8; i++) {
        mi[i] = g_mpart[(size_t)i * TOK + row];
        m = fmaxf(m, mi[i]);
    }
    float l = 0.f;
#pragma unroll
    for (int i = 0; i < 8; i++) {
        float sc = fast_exp(mi[i] - m);
        g_scale[(size_t)i * TOK + row] = sc;
        l += sc * g_lpart[(size_t)i * TOK + row];
    }
    g_l[row] = l;
}

// ------------------------------ prep kernels -------------------------------
__global__ void splitr_kernel(const float* __restrict__ feat) {
    __shared__ float sm[32][33];
    __shared__ float colsum[8][32];
    int b = blockIdx.z, t0 = blockIdx.x * 32, f0 = blockIdx.y * 32;
    int tx = threadIdx.x & 31, ty = threadIdx.x >> 5;
    float cs = 0.f;
#pragma unroll
    for (int i = 0; i < 4; i++) {
        int row = t0 + ty + 8 * i;
        size_t off = ((size_t)b * NT + row) * NF + f0 + tx;
        float v = feat[off];
        sm[ty + 8 * i][tx] = v;
        cs += v;
        __nv_bfloat16 h = __float2bfloat16(v);
        g_fhi[off] = h;
        g_flo[off] = __float2bfloat16(v - __bfloat162float(h));
    }
    colsum[ty][tx] = cs;
    __syncthreads();
#pragma unroll
    for (int i = 0; i < 4; i++) {
        float v = sm[tx][ty + 8 * i];
        size_t off = ((size_t)b * NF + f0 + ty + 8 * i) * NT + t0 + tx;
        g_fT16[off] = __float2half(v);
    }
    if (ty == 0) {
        float s = 0.f;
#pragma unroll
        for (int j = 0; j < 8; j++) s += colsum[j][tx];
        g_fsump[((size_t)b * 64 + blockIdx.x) * NF + f0 + tx] = s;
    }
}

__global__ void matM_kernel(const float* __restrict__ Wq, const float* __restrict__ Wk,
                            const float* __restrict__ bq) {
    int f = threadIdx.x;
    if (blockIdx.x < NF) {
        int fp = blockIdx.x;
        float s = 0.f;
        for (int g2 = 0; g2 < NF; g2++)
            s += Wq[g2 * NF + f] * __ldg(&Wk[g2 * NF + fp]);
        __nv_bfloat16 h = __float2bfloat16(s);
        g_Mhi[fp * NF + f] = h;
        g_Mlo[fp * NF + f] = __float2bfloat16(s - __bfloat162float(h));
    } else {
        float s = 0.f;
        for (int g2 = 0; g2 < NF; g2++)
            s += Wk[g2 * NF + f] * __ldg(&bq[g2]);
        g_u[f] = s;
    }
}

__global__ void beta_kernel(const float* __restrict__ feat) {
    int w = threadIdx.x >> 5, lane = threadIdx.x & 31;
    int tt = blockIdx.x * 8 + w;
    const float4* fr = reinterpret_cast<const float4*>(feat + (size_t)tt * NF);
    const float4* ur = reinterpret_cast<const float4*>(g_u);
    float s = 0.f;
#pragma unroll
    for (int i = 0; i < 2; i++) {
        float4 a = fr[lane + 32 * i], uu = ur[lane + 32 * i];
        s += a.x * uu.x + a.y * uu.y + a.z * uu.z + a.w * uu.w;
    }
#pragma unroll
    for (int off = 16; off; off >>= 1) s += __shfl_xor_sync(0xffffffffu, s, off);
    if (lane == 0) g_beta[tt] = s;
}

__global__ void combine_kernel(const float* __restrict__ Wq, const float* __restrict__ bq,
                               const float* __restrict__ Wk, const float* __restrict__ bk) {
    __shared__ float fs[NF], ks[NF];
    int b = blockIdx.x, tid = threadIdx.x;
    float s = 0.f;
#pragma unroll 8
    for (int p = 0; p < 64; p++) s += g_fsump[((size_t)b * 64 + p) * NF + tid];
    fs[tid] = s;
    __syncthreads();
    float kg = (float)NT * bk[tid];
    for (int f = 0; f < NF; f++) kg += Wk[tid * NF + f] * fs[f];
    ks[tid] = kg;
    __syncthreads();
    float vf = 0.f;
    for (int g2 = 0; g2 < NF; g2++) vf += Wq[g2 * NF + tid] * ks[g2];
    g_v[b * NF + tid] = vf;
    __syncthreads();
    fs[tid] = bq[tid] * ks[tid];
    __syncthreads();
    for (int off = 128; off; off >>= 1) {
        if (tid < off) fs[tid] += fs[tid + off];
        __syncthreads();
    }
    if (tid == 0) g_cc[b] = fs[0];
}

__global__ void score_kernel(const float* __restrict__ feat, float* __restrict__ out) {
    int w = threadIdx.x >> 5, lane = threadIdx.x & 31;
    int tt = blockIdx.x * 8 + w;
    int b = tt >> 11;
    const float4* fr = reinterpret_cast<const float4*>(feat + (size_t)tt * NF);
    const float4* vr = reinterpret_cast<const float4*>(g_v + b * NF);
    float s = 0.f;
#pragma unroll
    for (int i = 0; i < 2; i++) {
        float4 a = fr[lane + 32 * i], qv = vr[lane + 32 * i];
        s += a.x * qv.x + a.y * qv.y + a.z * qv.z + a.w * qv.w;
    }
#pragma unroll
    for (int off = 16; off; off >>= 1) s += __shfl_xor_sync(0xffffffffu, s, off);
    const size_t OFF_HLENS = (size_t)NB * NT * NF;
    if (lane == 0) out[OFF_HLENS + NB + tt] = (s + g_cc[b]) * (1.0f / NT);
    if (blockIdx.x == 0 && threadIdx.x < NB) out[OFF_HLENS + threadIdx.x] = (float)NT;
}

// ---------------------------------------------------------------------------
extern "C" void kernel_launch(void* const* d_in, const int* in_sizes, int n_in,
                              void* d_out, int out_size) {
    const float* feat = (const float*)d_in[0];
    const float* Wq = (const float*)d_in[2];
    const float* bq = (const float*)d_in[3];
    const float* Wk = (const float*)d_in[4];
    const float* bk = (const float*)d_in[5];
    float* out = (float*)d_out;

    cudaFuncSetAttribute(gemm_kernel<0>, cudaFuncAttributeMaxDynamicSharedMemorySize, 196608);
    cudaFuncSetAttribute(gemm_kernel<1>, cudaFuncAttributeMaxDynamicSharedMemorySize, 196608);
    cudaFuncSetAttribute(gemm2_kernel, cudaFuncAttributeMaxDynamicSharedMemorySize, 65536);

    // beta (needs g_u from matM) must precede gemm_kernel<1>; capture slot 4 = gemm0.
    splitr_kernel<<<dim3(NT / 32, NF / 32, NB), 256>>>(feat);
    matM_kernel<<<NF + 1, 256>>>(Wq, Wk, bq);
    beta_kernel<<<TOK / 8, 256>>>(feat);
    gemm_kernel<0><<<dim3(TOK / 128), 256, 196608>>>(out);
    gemm_kernel<1><<<dim3(NT / 256, NT / 128, NB), 256, 196608>>>(out);
    lsum_kernel<<<TOK / 256, 256>>>();
    gemm2_kernel<<<dim3(NT / 128, NF / 128, NB), 256, 65536>>>(out);
    combine_kernel<<<NB, 256>>>(Wq, bq, Wk, bk);
    score_kernel<<<TOK / 8, 256>>>(feat, out);
}

// round 17
// speedup vs baseline: 1.0215x; 1.0215x over previous
#include <cuda_runtime.h>
#include <cuda_bf16.h>
#include <cuda_fp16.h>
#include <stdint.h>

#define NB 8
#define NT 2048
#define NF 256
#define TOK (NB * NT)

// ------------------------------- device globals ---------------------------
__device__ __align__(128) __nv_bfloat16 g_fhi[TOK * NF], g_flo[TOK * NF];
__device__ __align__(128) __half g_fT16[(size_t)NB * NF * NT];
__device__ __align__(128) __nv_bfloat16 g_Ghi[TOK * NF], g_Glo[TOK * NF];
__device__ __align__(128) __nv_bfloat16 g_Mhi[NF * NF], g_Mlo[NF * NF];
__device__ __align__(128) __half g_p16[(size_t)NB * NT * NT];
__device__ __align__(128) float g_mpart[8 * TOK];
__device__ __align__(128) float g_lpart[8 * TOK];
__device__ __align__(128) float g_scale[8 * TOK];
__device__ __align__(128) float g_l[TOK];
__device__ __align__(128) float g_beta[TOK];
__device__ __align__(128) float g_u[NF];
__device__ float g_fsump[NB * 64 * NF];
__device__ float g_v[NB * NF];
__device__ float g_cc[NB];

// ------------------------------ helpers -----------------------------------
__device__ __forceinline__ uint32_t smem_u32(const void* p) {
    uint32_t a;
    asm("{ .reg .u64 t; cvta.to.shared.u64 t, %1; cvt.u32.u64 %0, t; }" : "=r"(a) : "l"(p));
    return a;
}
__device__ __forceinline__ uint32_t pack2(__nv_bfloat16 a, __nv_bfloat16 b) {
    __nv_bfloat162 t = __halves2bfloat162(a, b);
    return *reinterpret_cast<uint32_t*>(&t);
}
__device__ __forceinline__ uint32_t pack2h(__half a, __half b) {
    __half2 t = __halves2half2(a, b);
    return *reinterpret_cast<uint32_t*>(&t);
}
__device__ __forceinline__ float fast_exp(float x) {
    float t = x * 1.4426950408889634f;
    t = fmaxf(t, -125.0f);
    float r = t + 12582912.0f;
    int ei = __float_as_int(r) - 0x4B400000;
    float f = t - (r - 12582912.0f);
    float p = 1.5403530e-4f;
    p = fmaf(p, f, 1.3333558e-3f);
    p = fmaf(p, f, 9.6181291e-3f);
    p = fmaf(p, f, 5.5504109e-2f);
    p = fmaf(p, f, 2.4022651e-1f);
    p = fmaf(p, f, 6.9314718e-1f);
    p = fmaf(p, f, 1.0f);
    return p * __int_as_float((ei + 127) << 23);
}
__device__ __forceinline__ void cpa16(uint32_t d, const void* s) {
    asm volatile("cp.async.cg.shared.global [%0], [%1], 16;" :: "r"(d), "l"(s));
}
__device__ __forceinline__ void ldsm4(uint32_t a, uint32_t& r0, uint32_t& r1, uint32_t& r2, uint32_t& r3) {
    asm volatile("ldmatrix.sync.aligned.m8n8.x4.shared.b16 {%0,%1,%2,%3}, [%4];"
                 : "=r"(r0), "=r"(r1), "=r"(r2), "=r"(r3) : "r"(a));
}
__device__ __forceinline__ void mma_bf(float* c, const uint32_t* a, uint32_t b0, uint32_t b1) {
    asm volatile("mma.sync.aligned.m16n8k16.row.col.f32.bf16.bf16.f32 "
                 "{%0,%1,%2,%3},{%4,%5,%6,%7},{%8,%9},{%0,%1,%2,%3};"
                 : "+f"(c[0]), "+f"(c[1]), "+f"(c[2]), "+f"(c[3])
                 : "r"(a[0]), "r"(a[1]), "r"(a[2]), "r"(a[3]), "r"(b0), "r"(b1));
}
__device__ __forceinline__ void mma_hf(float* c, const uint32_t* a, uint32_t b0, uint32_t b1) {
    asm volatile("mma.sync.aligned.m16n8k16.row.col.f32.f16.f16.f32 "
                 "{%0,%1,%2,%3},{%4,%5,%6,%7},{%8,%9},{%0,%1,%2,%3};"
                 : "+f"(c[0]), "+f"(c[1]), "+f"(c[2]), "+f"(c[3])
                 : "r"(a[0]), "r"(a[1]), "r"(a[2]), "r"(a[3]), "r"(b0), "r"(b1));
}

template <int ROWS>
__device__ __forceinline__ void load_slice(uint32_t dst, const __nv_bfloat16* __restrict__ src, int ld) {
#pragma unroll
    for (int it = 0; it < ROWS * 8 / 256; it++) {
        int idx = it * 256 + threadIdx.x;
        int r = idx >> 3, c = idx & 7;
        uint32_t d = dst + ((r >> 3) << 10) + ((r & 7) << 7) + ((uint32_t)(c ^ (r & 7)) << 4);
        cpa16(d, src + (size_t)r * ld + c * 8);
    }
}
__device__ __forceinline__ uint32_t frag_addr(uint32_t base, int r, int c) {
    return base + ((r >> 3) << 10) + ((r & 7) << 7) + ((uint32_t)(c ^ (r & 7)) << 4);
}

// ---------------------------------------------------------------------------
// Split-bf16 GEMM (MODE 0/1): D[128,256], 256 thr, 8 warps (2M x 4N), warp 64x64.
// MODE 0: G = feat @ M~^T, K=256 -> G hi/lo
// MODE 1: G1 = G @ feat^T + beta, K=256 -> P_local fp16 + m,l partials
// ---------------------------------------------------------------------------
template <int MODE>
__global__ void __launch_bounds__(256, 1) gemm_kernel(float* __restrict__ out) {
    extern __shared__ char smem[];
    uint32_t sb = smem_u32(smem);
    const int tid = threadIdx.x, wid = tid >> 5, lane = tid & 31;
    constexpr int NS = 4;
    constexpr uint32_t STAGE = 98304u;

    const __nv_bfloat16 *Ahi, *Alo, *Bhi, *Blo;
    int m0, n0 = 0, b = 0;
    if (MODE == 0) {
        m0 = blockIdx.x * 128;
        Ahi = g_fhi + (size_t)m0 * NF; Alo = g_flo + (size_t)m0 * NF;
        Bhi = g_Mhi; Blo = g_Mlo;
    } else {
        n0 = blockIdx.x * 256; m0 = blockIdx.y * 128; b = blockIdx.z;
        Ahi = g_Ghi + (size_t)(b * NT + m0) * NF; Alo = g_Glo + (size_t)(b * NT + m0) * NF;
        Bhi = g_fhi + (size_t)(b * NT + n0) * NF; Blo = g_flo + (size_t)(b * NT + n0) * NF;
    }

    const int wm = (wid & 1) << 6;
    const int wn = (wid >> 1) << 6;
    const int g = lane >> 2, q = lane & 3;

    float acc[4][8][4];
#pragma unroll
    for (int i = 0; i < 4; i++)
#pragma unroll
        for (int j = 0; j < 8; j++)
#pragma unroll
            for (int u = 0; u < 4; u++) acc[i][j][u] = 0.f;

    auto load_stage = [&](int s) {
        uint32_t base = sb + (uint32_t)(s & 1) * STAGE;
        load_slice<128>(base,          Ahi + s * 64, NF);
        load_slice<128>(base + 16384,  Alo + s * 64, NF);
        load_slice<256>(base + 32768,  Bhi + s * 64, NF);
        load_slice<256>(base + 65536,  Blo + s * 64, NF);
        asm volatile("cp.async.commit_group;");
    };

    load_stage(0);

#pragma unroll 1
    for (int s = 0; s < NS; s++) {
        if (s + 1 < NS) {
            load_stage(s + 1);
            asm volatile("cp.async.wait_group 1;");
        } else {
            asm volatile("cp.async.wait_group 0;");
        }
        __syncthreads();

        uint32_t base = sb + (uint32_t)(s & 1) * STAGE;
        const int ar = wm + (lane & 15), br = wn + (lane & 15), ch = lane >> 4;
#pragma unroll
        for (int k = 0; k < 4; k++) {
            const int c = 2 * k + ch;
            uint32_t ah[4][4], bh[4][4], tt[4][4];
#pragma unroll
            for (int mt = 0; mt < 4; mt++)
                ldsm4(frag_addr(base, ar + 16 * mt, c), ah[mt][0], ah[mt][1], ah[mt][2], ah[mt][3]);
#pragma unroll
            for (int nt = 0; nt < 4; nt++)
                ldsm4(frag_addr(base + 32768u, br + 16 * nt, c), bh[nt][0], bh[nt][1], bh[nt][2], bh[nt][3]);
            // pass hh
#pragma unroll
            for (int nt = 0; nt < 4; nt++)
#pragma unroll
                for (int mt = 0; mt < 4; mt++) {
                    mma_bf(acc[mt][2 * nt],     ah[mt], bh[nt][0], bh[nt][2]);
                    mma_bf(acc[mt][2 * nt + 1], ah[mt], bh[nt][1], bh[nt][3]);
                }
            // pass hl: B-lo, reuse ah
#pragma unroll
            for (int nt = 0; nt < 4; nt++)
                ldsm4(frag_addr(base + 65536u, br + 16 * nt, c), tt[nt][0], tt[nt][1], tt[nt][2], tt[nt][3]);
#pragma unroll
            for (int nt = 0; nt < 4; nt++)
#pragma unroll
                for (int mt = 0; mt < 4; mt++) {
                    mma_bf(acc[mt][2 * nt],     ah[mt], tt[nt][0], tt[nt][2]);
                    mma_bf(acc[mt][2 * nt + 1], ah[mt], tt[nt][1], tt[nt][3]);
                }
            // pass lh: A-lo, reuse bh
#pragma unroll
            for (int mt = 0; mt < 4; mt++)
                ldsm4(frag_addr(base + 16384u, ar + 16 * mt, c), tt[mt][0], tt[mt][1], tt[mt][2], tt[mt][3]);
#pragma unroll
            for (int nt = 0; nt < 4; nt++)
#pragma unroll
                for (int mt = 0; mt < 4; mt++) {
                    mma_bf(acc[mt][2 * nt],     tt[mt], bh[nt][0], bh[nt][2]);
                    mma_bf(acc[mt][2 * nt + 1], tt[mt], bh[nt][1], bh[nt][3]);
                }
        }
        __syncthreads();
    }

    // ------------------------------ epilogues ------------------------------
    if (MODE == 0) {
#pragma unroll
        for (int mt = 0; mt < 4; mt++) {
            int ra = m0 + wm + 16 * mt + g, rb = ra + 8;
#pragma unroll
            for (int nt = 0; nt < 8; nt++) {
                int col = wn + nt * 8 + 2 * q;
                float v0 = acc[mt][nt][0], v1 = acc[mt][nt][1];
                float v2 = acc[mt][nt][2], v3 = acc[mt][nt][3];
                __nv_bfloat16 h0 = __float2bfloat16(v0), h1 = __float2bfloat16(v1);
                __nv_bfloat16 h2 = __float2bfloat16(v2), h3 = __float2bfloat16(v3);
                *reinterpret_cast<uint32_t*>(&g_Ghi[(size_t)ra * NF + col]) = pack2(h0, h1);
                *reinterpret_cast<uint32_t*>(&g_Ghi[(size_t)rb * NF + col]) = pack2(h2, h3);
                *reinterpret_cast<uint32_t*>(&g_Glo[(size_t)ra * NF + col]) =
                    pack2(__float2bfloat16(v0 - __bfloat162float(h0)), __float2bfloat16(v1 - __bfloat162float(h1)));
                *reinterpret_cast<uint32_t*>(&g_Glo[(size_t)rb * NF + col]) =
                    pack2(__float2bfloat16(v2 - __bfloat162float(h2)), __float2bfloat16(v3 - __bfloat162float(h3)));
            }
        }
    } else {
        float* ls  = reinterpret_cast<float*>(smem);
        float* ls2 = reinterpret_cast<float*>(smem) + 512;
        float2 be[8];
#pragma unroll
        for (int nt = 0; nt < 8; nt++)
            be[nt] = *reinterpret_cast<const float2*>(&g_beta[b * NT + n0 + wn + nt * 8 + 2 * q]);
#pragma unroll
        for (int mt = 0; mt < 4; mt++) {
            float ma = -1e30f, mb = -1e30f;
#pragma unroll
            for (int nt = 0; nt < 8; nt++) {
                acc[mt][nt][0] += be[nt].x; acc[mt][nt][1] += be[nt].y;
                acc[mt][nt][2] += be[nt].x; acc[mt][nt][3] += be[nt].y;
                ma = fmaxf(ma, fmaxf(acc[mt][nt][0], acc[mt][nt][1]));
                mb = fmaxf(mb, fmaxf(acc[mt][nt][2], acc[mt][nt][3]));
            }
#pragma unroll
            for (int off = 1; off <= 2; off <<= 1) {
                ma = fmaxf(ma, __shfl_xor_sync(0xffffffffu, ma, off));
                mb = fmaxf(mb, __shfl_xor_sync(0xffffffffu, mb, off));
            }
            if (q == 0) {
                int lr = wm + 16 * mt + g;
                ls[(size_t)lr * 4 + (wid >> 1)] = ma;
                ls[(size_t)(lr + 8) * 4 + (wid >> 1)] = mb;
            }
        }
        __syncthreads();
#pragma unroll
        for (int mt = 0; mt < 4; mt++) {
            int lra = wm + 16 * mt + g, lrb = lra + 8;
            float mla = fmaxf(fmaxf(ls[lra * 4], ls[lra * 4 + 1]),
                              fmaxf(ls[lra * 4 + 2], ls[lra * 4 + 3]));
            float mlb = fmaxf(fmaxf(ls[lrb * 4], ls[lrb * 4 + 1]),
                              fmaxf(ls[lrb * 4 + 2], ls[lrb * 4 + 3]));
            int ra = m0 + lra, rb = m0 + lrb;
            float sa = 0.f, sbn = 0.f;
#pragma unroll
            for (int nt = 0; nt < 8; nt++) {
                int col = n0 + wn + nt * 8 + 2 * q;
                float p0 = fast_exp(acc[mt][nt][0] - mla);
                float p1 = fast_exp(acc[mt][nt][1] - mla);
                float p2 = fast_exp(acc[mt][nt][2] - mlb);
                float p3 = fast_exp(acc[mt][nt][3] - mlb);
                sa += p0 + p1; sbn += p2 + p3;
                *reinterpret_cast<uint32_t*>(&g_p16[((size_t)b * NT + ra) * NT + col]) =
                    pack2h(__float2half(p0), __float2half(p1));
                *reinterpret_cast<uint32_t*>(&g_p16[((size_t)b * NT + rb) * NT + col]) =
                    pack2h(__float2half(p2), __float2half(p3));
            }
#pragma unroll
            for (int off = 1; off <= 2; off <<= 1) {
                sa += __shfl_xor_sync(0xffffffffu, sa, off);
                sbn += __shfl_xor_sync(0xffffffffu, sbn, off);
            }
            if (q == 0) {
                ls2[(size_t)lra * 4 + (wid >> 1)] = sa;
                ls2[(size_t)lrb * 4 + (wid >> 1)] = sbn;
            }
        }
        __syncthreads();
        if (tid < 128) {
            float m = fmaxf(fmaxf(ls[tid * 4], ls[tid * 4 + 1]),
                            fmaxf(ls[tid * 4 + 2], ls[tid * 4 + 3]));
            float l = ls2[tid * 4] + ls2[tid * 4 + 1] + ls2[tid * 4 + 2] + ls2[tid * 4 + 3];
            g_mpart[(size_t)blockIdx.x * TOK + b * NT + m0 + tid] = m;
            g_lpart[(size_t)blockIdx.x * TOK + b * NT + m0 + tid] = l;
        }
    }
}

// ---------------------------------------------------------------------------
// G2: out = (P_local * scale) @ featT / l. CTA 128x128, 256 thr,
// warp grid 2M x 4N (warp tile 64x32), 2 CTAs/SM, 3-deep cp.async pipeline.
// ---------------------------------------------------------------------------
__global__ void __launch_bounds__(256, 2) gemm2_kernel(float* __restrict__ out) {
    extern __shared__ char smem[];
    uint32_t sb = smem_u32(smem);
    const int tid = threadIdx.x, wid = tid >> 5, lane = tid & 31;
    constexpr int NS = 32;
    constexpr uint32_t STAGE = 32768u;  // A 16K + B 16K, x3 stages = 96KB

    const int m0 = blockIdx.x * 128, n0 = blockIdx.y * 128, b = blockIdx.z;
    const __nv_bfloat16* A = reinterpret_cast<const __nv_bfloat16*>(g_p16 + ((size_t)b * NT + m0) * NT);
    const __nv_bfloat16* B = reinterpret_cast<const __nv_bfloat16*>(g_fT16 + ((size_t)b * NF + n0) * NT);

    const int wm = (wid & 1) << 6;
    const int wn = (wid >> 1) << 5;
    const int g = lane >> 2, q = lane & 3;

    float acc[4][4][4];
#pragma unroll
    for (int i = 0; i < 4; i++)
#pragma unroll
        for (int j = 0; j < 4; j++)
#pragma unroll
            for (int u = 0; u < 4; u++) acc[i][j][u] = 0.f;

    auto stage_base = [&](int s) -> uint32_t {
        int slot = s % 3;
        return sb + (uint32_t)slot * STAGE;
    };
    auto load_stage = [&](int s) {
        uint32_t base = stage_base(s);
        load_slice<128>(base,          A + s * 64, NT);
        load_slice<128>(base + 16384,  B + s * 64, NT);
        asm volatile("cp.async.commit_group;");
    };

    load_stage(0);
    load_stage(1);

    __half2 sca2[4], scb2[4];

#pragma unroll 1
    for (int s = 0; s < NS; s++) {
        if ((s & 3) == 0) {
            int tile = s >> 2;
#pragma unroll
            for (int mt = 0; mt < 4; mt++) {
                int ra = m0 + wm + 16 * mt + g;
                sca2[mt] = __float2half2_rn(g_scale[(size_t)tile * TOK + b * NT + ra]);
                scb2[mt] = __float2half2_rn(g_scale[(size_t)tile * TOK + b * NT + ra + 8]);
            }
        }
        if (s + 2 < NS) {
            load_stage(s + 2);
            asm volatile("cp.async.wait_group 2;");
        } else if (s + 1 < NS) {
            asm volatile("cp.async.wait_group 1;");
        } else {
            asm volatile("cp.async.wait_group 0;");
        }
        __syncthreads();

        uint32_t base = stage_base(s);
        const int ar = wm + (lane & 15), br = wn + (lane & 15), ch = lane >> 4;
#pragma unroll
        for (int k = 0; k < 4; k++) {
            const int c = 2 * k + ch;
            uint32_t a4[4][4], b4[2][4];
#pragma unroll
            for (int mt = 0; mt < 4; mt++) {
                ldsm4(frag_addr(base, ar + 16 * mt, c), a4[mt][0], a4[mt][1], a4[mt][2], a4[mt][3]);
                __half2* ap = reinterpret_cast<__half2*>(a4[mt]);
                ap[0] = __hmul2(ap[0], sca2[mt]);
                ap[2] = __hmul2(ap[2], sca2[mt]);
                ap[1] = __hmul2(ap[1], scb2[mt]);
                ap[3] = __hmul2(ap[3], scb2[mt]);
            }
#pragma unroll
            for (int j = 0; j < 2; j++)
                ldsm4(frag_addr(base + 16384u, br + 16 * j, c), b4[j][0], b4[j][1], b4[j][2], b4[j][3]);
#pragma unroll
            for (int j = 0; j < 2; j++)
#pragma unroll
                for (int mt = 0; mt < 4; mt++) {
                    mma_hf(acc[mt][2 * j],     a4[mt], b4[j][0], b4[j][2]);
                    mma_hf(acc[mt][2 * j + 1], a4[mt], b4[j][1], b4[j][3]);
                }
        }
        __syncthreads();
    }

#pragma unroll
    for (int mt = 0; mt < 4; mt++) {
        int ra = m0 + wm + 16 * mt + g, rb = ra + 8;
        float ia = 1.0f / g_l[b * NT + ra];
        float ib = 1.0f / g_l[b * NT + rb];
#pragma unroll
        for (int nt = 0; nt < 4; nt++) {
            int col = n0 + wn + nt * 8 + 2 * q;
            float2 wa, wb;
            wa.x = acc[mt][nt][0] * ia; wa.y = acc[mt][nt][1] * ia;
            wb.x = acc[mt][nt][2] * ib; wb.y = acc[mt][nt][3] * ib;
            *reinterpret_cast<float2*>(&out[((size_t)b * NT + ra) * NF + col]) = wa;
            *reinterpret_cast<float2*>(&out[((size_t)b * NT + rb) * NF + col]) = wb;
        }
    }
}

// ---------------------- lsum: exact row max/sum + scales --------------------
__global__ void lsum_kernel() {
    int row = blockIdx.x * 256 + threadIdx.x;
    float mi[8], m = -1e30f;
#pragma unroll
    for (int i = 0; i < 8; i++) {
        mi[i] = g_mpart[(size_t)i * TOK + row];
        m = fmaxf(m, mi[i]);
    }
    float l = 0.f;
#pragma unroll
    for (int i = 0; i < 8; i++) {
        float sc = fast_exp(mi[i] - m);
        g_scale[(size_t)i * TOK + row] = sc;
        l += sc * g_lpart[(size_t)i * TOK + row];
    }
    g_l[row] = l;
}

// ------------------------------ prep kernels -------------------------------
__global__ void splitr_kernel(const float* __restrict__ feat) {
    __shared__ float sm[32][33];
    __shared__ float colsum[8][32];
    int b = blockIdx.z, t0 = blockIdx.x * 32, f0 = blockIdx.y * 32;
    int tx = threadIdx.x & 31, ty = threadIdx.x >> 5;
    float cs = 0.f;
#pragma unroll
    for (int i = 0; i < 4; i++) {
        int row = t0 + ty + 8 * i;
        size_t off = ((size_t)b * NT + row) * NF + f0 + tx;
        float v = feat[off];
        sm[ty + 8 * i][tx] = v;
        cs += v;
        __nv_bfloat16 h = __float2bfloat16(v);
        g_fhi[off] = h;
        g_flo[off] = __float2bfloat16(v - __bfloat162float(h));
    }
    colsum[ty][tx] = cs;
    __syncthreads();
#pragma unroll
    for (int i = 0; i < 4; i++) {
        float v = sm[tx][ty + 8 * i];
        size_t off = ((size_t)b * NF + f0 + ty + 8 * i) * NT + t0 + tx;
        g_fT16[off] = __float2half(v);
    }
    if (ty == 0) {
        float s = 0.f;
#pragma unroll
        for (int j = 0; j < 8; j++) s += colsum[j][tx];
        g_fsump[((size_t)b * 64 + blockIdx.x) * NF + f0 + tx] = s;
    }
}

__global__ void matM_kernel(const float* __restrict__ Wq, const float* __restrict__ Wk,
                            const float* __restrict__ bq) {
    int f = threadIdx.x;
    if (blockIdx.x < NF) {
        int fp = blockIdx.x;
        float s = 0.f;
        for (int g2 = 0; g2 < NF; g2++)
            s += Wq[g2 * NF + f] * __ldg(&Wk[g2 * NF + fp]);
        __nv_bfloat16 h = __float2bfloat16(s);
        g_Mhi[fp * NF + f] = h;
        g_Mlo[fp * NF + f] = __float2bfloat16(s - __bfloat162float(h));
    } else {
        float s = 0.f;
        for (int g2 = 0; g2 < NF; g2++)
            s += Wk[g2 * NF + f] * __ldg(&bq[g2]);
        g_u[f] = s;
    }
}

__global__ void beta_kernel(const float* __restrict__ feat) {
    int w = threadIdx.x >> 5, lane = threadIdx.x & 31;
    int tt = blockIdx.x * 8 + w;
    const float4* fr = reinterpret_cast<const float4*>(feat + (size_t)tt * NF);
    const float4* ur = reinterpret_cast<const float4*>(g_u);
    float s = 0.f;
#pragma unroll
    for (int i = 0; i < 2; i++) {
        float4 a = fr[lane + 32 * i], uu = ur[lane + 32 * i];
        s += a.x * uu.x + a.y * uu.y + a.z * uu.z + a.w * uu.w;
    }
#pragma unroll
    for (int off = 16; off; off >>= 1) s += __shfl_xor_sync(0xffffffffu, s, off);
    if (lane == 0) g_beta[tt] = s;
}

__global__ void combine_kernel(const float* __restrict__ Wq, const float* __restrict__ bq,
                               const float* __restrict__ Wk, const float* __restrict__ bk) {
    __shared__ float fs[NF], ks[NF];
    int b = blockIdx.x, tid = threadIdx.x;
    float s = 0.f;
#pragma unroll 8
    for (int p = 0; p < 64; p++) s += g_fsump[((size_t)b * 64 + p) * NF + tid];
    fs[tid] = s;
    __syncthreads();
    float kg = (float)NT * bk[tid];
    for (int f = 0; f < NF; f++) kg += Wk[tid * NF + f] * fs[f];
    ks[tid] = kg;
    __syncthreads();
    float vf = 0.f;
    for (int g2 = 0; g2 < NF; g2++) vf += Wq[g2 * NF + tid] * ks[g2];
    g_v[b * NF + tid] = vf;
    __syncthreads();
    fs[tid] = bq[tid] * ks[tid];
    __syncthreads();
    for (int off = 128; off; off >>= 1) {
        if (tid < off) fs[tid] += fs[tid + off];
        __syncthreads();
    }
    if (tid == 0) g_cc[b] = fs[0];
}

__global__ void score_kernel(const float* __restrict__ feat, float* __restrict__ out) {
    int w = threadIdx.x >> 5, lane = threadIdx.x & 31;
    int tt = blockIdx.x * 8 + w;
    int b = tt >> 11;
    const float4* fr = reinterpret_cast<const float4*>(feat + (size_t)tt * NF);
    const float4* vr = reinterpret_cast<const float4*>(g_v + b * NF);
    float s = 0.f;
#pragma unroll
    for (int i = 0; i < 2; i++) {
        float4 a = fr[lane + 32 * i], qv = vr[lane + 32 * i];
        s += a.x * qv.x + a.y * qv.y + a.z * qv.z + a.w * qv.w;
    }
#pragma unroll
    for (int off = 16; off; off >>= 1) s += __shfl_xor_sync(0xffffffffu, s, off);
    const size_t OFF_HLENS = (size_t)NB * NT * NF;
    if (lane == 0) out[OFF_HLENS + NB + tt] = (s + g_cc[b]) * (1.0f / NT);
    if (blockIdx.x == 0 && threadIdx.x < NB) out[OFF_HLENS + threadIdx.x] = (float)NT;
}

// ---------------------------------------------------------------------------
extern "C" void kernel_launch(void* const* d_in, const int* in_sizes, int n_in,
                              void* d_out, int out_size) {
    const float* feat = (const float*)d_in[0];
    const float* Wq = (const float*)d_in[2];
    const float* bq = (const float*)d_in[3];
    const float* Wk = (const float*)d_in[4];
    const float* bk = (const float*)d_in[5];
    float* out = (float*)d_out;

    cudaFuncSetAttribute(gemm_kernel<0>, cudaFuncAttributeMaxDynamicSharedMemorySize, 196608);
    cudaFuncSetAttribute(gemm_kernel<1>, cudaFuncAttributeMaxDynamicSharedMemorySize, 196608);
    cudaFuncSetAttribute(gemm2_kernel, cudaFuncAttributeMaxDynamicSharedMemorySize, 98304);

    splitr_kernel<<<dim3(NT / 32, NF / 32, NB), 256>>>(feat);
    matM_kernel<<<NF + 1, 256>>>(Wq, Wk, bq);
    beta_kernel<<<TOK / 8, 256>>>(feat);
    gemm_kernel<0><<<dim3(TOK / 128), 256, 196608>>>(out);
    gemm_kernel<1><<<dim3(NT / 256, NT / 128, NB), 256, 196608>>>(out);
    lsum_kernel<<<TOK / 256, 256>>>();
    gemm2_kernel<<<dim3(NT / 128, NF / 128, NB), 256, 98304>>>(out);
    combine_kernel<<<NB, 256>>>(Wq, bq, Wk, bk);
    score_kernel<<<TOK / 8, 256>>>(feat, out);
}